// round 12
// baseline (speedup 1.0000x reference)
#include <cuda_runtime.h>
#include <cuda_bf16.h>
#include <math.h>

#define PI_D 3.14159265358979323846
typedef unsigned long long u64;
typedef unsigned int u32;
typedef unsigned short u16;

__device__ __forceinline__ u64 pack2(float lo, float hi) {
    u64 r; asm("mov.b64 %0,{%1,%2};" : "=l"(r) : "f"(lo), "f"(hi)); return r;
}
__device__ __forceinline__ float2 unpk(u64 v) {
    float2 f; asm("mov.b64 {%0,%1},%2;" : "=f"(f.x), "=f"(f.y) : "l"(v)); return f;
}
__device__ __forceinline__ void fma2(u64& d, u64 a, u64 b) {
    asm("fma.rn.f32x2 %0,%1,%2,%0;" : "+l"(d) : "l"(a), "l"(b));
}
__device__ __forceinline__ void mma16816(float* c, const u32* a, u32 b0, u32 b1) {
    asm volatile("mma.sync.aligned.m16n8k16.row.col.f32.bf16.bf16.f32 "
        "{%0,%1,%2,%3},{%4,%5,%6,%7},{%8,%9},{%0,%1,%2,%3};"
        : "+f"(c[0]), "+f"(c[1]), "+f"(c[2]), "+f"(c[3])
        : "r"(a[0]), "r"(a[1]), "r"(a[2]), "r"(a[3]), "r"(b0), "r"(b1));
}
__device__ __forceinline__ u32 bfsplit(float x, float y, u32& lo) {
    __nv_bfloat162 h = __floats2bfloat162_rn(x, y);
    float2 f = __bfloat1622float2(h);
    __nv_bfloat162 l = __floats2bfloat162_rn(x - f.x, y - f.y);
    lo = *(u32*)&l; return *(u32*)&h;
}

// ----------------------------- device scratch ------------------------------
__device__ float g_Ft [256 * 64];
__device__ float g_Cit[256 * 64];
__device__ float g_w1t[2 * 32 * 64 * 64];
__device__ float g_w2t[2 * 32 * 64 * 64];
__device__ float g_S[(size_t)4096 * 4096];
__device__ float g_T[(size_t)4096 * 4096];
__device__ float g_Z[(size_t)1048576 * 64];
__device__ u16 g_W1s[2 * 16384];
__device__ u16 g_W2s[2 * 16384];

__global__ void k_basis() {
    int idx = blockIdx.x * 256 + threadIdx.x;
    if (idx >= 16384) return;
    int n = idx >> 6, kr = idx & 63, k = kr >> 1;
    double th = 2.0 * PI_D * (double)k * (double)n / 256.0;
    double c = cos(th), s = sin(th);
    g_Ft[idx] = (float)(((kr & 1) ? -s : c) * 0.0625);
    double v;
    if (k == 0) v = (kr & 1) ? 0.0 : 0.0625;
    else        v = ((kr & 1) ? -2.0 * s : 2.0 * c) * 0.0625;
    g_Cit[idx] = (float)v;
}

__global__ void k_wt(const float* __restrict__ w1re, const float* __restrict__ w1im,
                     const float* __restrict__ w2re, const float* __restrict__ w2im) {
    int idx = blockIdx.x * 256 + threadIdx.x;
    if (idx >= 131072) return;
    int k = idx >> 12, c = (idx >> 6) & 63, o = idx & 63;
    int src = (c * 64 + o) * 32 + k;
    g_w1t[idx] = w1re[src]; g_w1t[131072 + idx] = w1im[src];
    g_w2t[idx] = w2re[src]; g_w2t[131072 + idx] = w2im[src];
}

__global__ void k_prep(const float* __restrict__ ffw1, const float* __restrict__ ffw2) {
    int idx = blockIdx.x * 256 + threadIdx.x;
    if (idx >= 16384) return;
    {
        int j = idx >> 6, c = idx & 63;
        float v = ffw1[c * 256 + j];
        __nv_bfloat16 h = __float2bfloat16(v);
        __nv_bfloat16 l = __float2bfloat16(v - __bfloat162float(h));
        g_W1s[idx] = *(u16*)&h; g_W1s[16384 + idx] = *(u16*)&l;
    }
    {
        int o = idx >> 8, j = idx & 255;
        float v = ffw2[j * 64 + o];
        __nv_bfloat16 h = __float2bfloat16(v);
        __nv_bfloat16 l = __float2bfloat16(v - __bfloat162float(h));
        g_W2s[idx] = *(u16*)&h; g_W2s[16384 + idx] = *(u16*)&l;
    }
}

// --------------------- forward DFT GEMM (unchanged) -------------------------
__global__ __launch_bounds__(256) void k_fwd(const float* __restrict__ x, int xpath) {
    extern __shared__ float sm[];
    float* fs = sm;
    float* xs = sm + 8192;
    int t = threadIdx.x;
    int sl = t >> 7, s = t & 127;
    int tx = s & 15, ty = s >> 4;
    int slab0 = blockIdx.x * 2;
    u64 acc[4][4] = {};
    for (int h = 0; h < 2; h++) {
        for (int i = t; i < 2048; i += 256)
            ((float4*)fs)[i] = ((const float4*)g_Ft)[h * 2048 + i];
        if (!xpath) {
            for (int i = t; i < 4096; i += 256) {
                int ssl = i >> 11, j = i & 2047;
                ((float4*)xs)[i] = *((const float4*)(x + (size_t)(slab0 + ssl) * 16384u + (size_t)h * 8192u) + j);
            }
        } else {
            for (int i = t; i < 4096; i += 256) {
                int ssl = i >> 11, j = i & 2047;
                int mm = j >> 4, c4 = (j & 15) * 4;
                int slab = slab0 + ssl;
                size_t base = (size_t)(slab >> 8) * 4194304u + (size_t)(slab & 255) * 64u;
                ((float4*)xs)[i] = *(const float4*)(x + base + (size_t)(h * 128 + mm) * 16384u + c4);
            }
        }
        __syncthreads();
        const float* fb = fs + ty * 8;
        const float* xb = xs + sl * 8192 + tx * 4;
#pragma unroll 4
        for (int n = 0; n < 128; n++) {
            u64 f0 = *(const u64*)(fb + n * 64 + 0);
            u64 f1 = *(const u64*)(fb + n * 64 + 2);
            u64 f2 = *(const u64*)(fb + n * 64 + 4);
            u64 f3 = *(const u64*)(fb + n * 64 + 6);
            float4 xv = *(const float4*)(xb + n * 64);
            u64 x0 = pack2(xv.x, xv.x), x1 = pack2(xv.y, xv.y);
            u64 x2 = pack2(xv.z, xv.z), x3 = pack2(xv.w, xv.w);
            fma2(acc[0][0], f0, x0); fma2(acc[0][1], f0, x1);
            fma2(acc[0][2], f0, x2); fma2(acc[0][3], f0, x3);
            fma2(acc[1][0], f1, x0); fma2(acc[1][1], f1, x1);
            fma2(acc[1][2], f1, x2); fma2(acc[1][3], f1, x3);
            fma2(acc[2][0], f2, x0); fma2(acc[2][1], f2, x1);
            fma2(acc[2][2], f2, x2); fma2(acc[2][3], f2, x3);
            fma2(acc[3][0], f3, x0); fma2(acc[3][1], f3, x1);
            fma2(acc[3][2], f3, x2); fma2(acc[3][3], f3, x3);
        }
        __syncthreads();
    }
    float* Sp = g_S + (size_t)(slab0 + sl) * 4096u + (size_t)(ty * 8) * 64u + tx * 4;
#pragma unroll
    for (int p = 0; p < 4; p++) {
        float2 a0 = unpk(acc[p][0]), a1 = unpk(acc[p][1]);
        float2 a2 = unpk(acc[p][2]), a3 = unpk(acc[p][3]);
        *(float4*)(Sp + (2 * p) * 64)     = make_float4(a0.x, a1.x, a2.x, a3.x);
        *(float4*)(Sp + (2 * p + 1) * 64) = make_float4(a0.y, a1.y, a2.y, a3.y);
    }
}

// --------------------- per-mode complex mix (unchanged) ---------------------
__global__ __launch_bounds__(256) void k_mix(int which) {
    extern __shared__ float sm[];
    float* Ss  = sm;
    float* Wre = sm + 64 * 132;
    float* Wim = Wre + 4096;
    const float* wt = which ? g_w2t : g_w1t;
    int t = threadIdx.x;
    int k = blockIdx.y;
    int s0 = blockIdx.x * 64;
    for (int i = t; i < 2048; i += 256) {
        int s = i >> 5, q = (i & 31) * 4;
        float4 v = *(const float4*)(g_S + (size_t)(s0 + s) * 4096u + (size_t)k * 128u + q);
        *(float4*)(Ss + s * 132 + q) = v;
    }
    for (int i = t; i < 1024; i += 256) {
        ((float4*)Wre)[i] = *(const float4*)(wt + (size_t)k * 4096u + i * 4);
        ((float4*)Wim)[i] = *(const float4*)(wt + 131072u + (size_t)k * 4096u + i * 4);
    }
    __syncthreads();
    int tx = t & 15, ty = t >> 4;
    u64 ar[4][2] = {}, ai[4][2] = {};
#pragma unroll 4
    for (int c = 0; c < 64; c++) {
        ulonglong2 wr = *(const ulonglong2*)(Wre + c * 64 + tx * 4);
        ulonglong2 wi = *(const ulonglong2*)(Wim + c * 64 + tx * 4);
#pragma unroll
        for (int i = 0; i < 4; i++) {
            float srv = Ss[(ty * 4 + i) * 132 + c];
            float siv = Ss[(ty * 4 + i) * 132 + 64 + c];
            u64 sr2 = pack2(srv, srv), si2 = pack2(siv, siv), ns2 = pack2(-siv, -siv);
            fma2(ar[i][0], sr2, wr.x); fma2(ar[i][0], ns2, wi.x);
            fma2(ar[i][1], sr2, wr.y); fma2(ar[i][1], ns2, wi.y);
            fma2(ai[i][0], sr2, wi.x); fma2(ai[i][0], si2, wr.x);
            fma2(ai[i][1], sr2, wi.y); fma2(ai[i][1], si2, wr.y);
        }
    }
#pragma unroll
    for (int i = 0; i < 4; i++) {
        float* Tp = g_T + (size_t)(s0 + ty * 4 + i) * 4096u + (size_t)(2 * k) * 64u + tx * 4;
        float2 r0 = unpk(ar[i][0]), r1 = unpk(ar[i][1]);
        float2 m0 = unpk(ai[i][0]), m1 = unpk(ai[i][1]);
        *(float4*)Tp        = make_float4(r0.x, r0.y, r1.x, r1.y);
        *(float4*)(Tp + 64) = make_float4(m0.x, m0.y, m1.x, m1.y);
    }
}

// --------------------- inverse DFT GEMM (unchanged) -------------------------
__global__ __launch_bounds__(256) void k_inv(int xpath) {
    extern __shared__ float sm[];
    float* Cs = sm;
    float* Ts = sm + 16640;
    int t = threadIdx.x;
    int slab = blockIdx.x;
    for (int i = t; i < 16384; i += 256)
        Cs[(i >> 6) * 65 + (i & 63)] = g_Cit[i];
    {
        const float4* tsrc = (const float4*)(g_T + (size_t)slab * 4096u);
        for (int i = t; i < 1024; i += 256) ((float4*)Ts)[i] = tsrc[i];
    }
    __syncthreads();
    int tx = t & 7, ty = t >> 3;
    int n0 = ty * 8;
    u64 acc[8][4] = {};
#pragma unroll 2
    for (int kr = 0; kr < 64; kr++) {
        ulonglong2 t0 = *(const ulonglong2*)(Ts + kr * 64 + tx * 4);
        ulonglong2 t1 = *(const ulonglong2*)(Ts + kr * 64 + 32 + tx * 4);
#pragma unroll
        for (int i = 0; i < 8; i++) {
            float cv = Cs[(n0 + i) * 65 + kr];
            u64 c2 = pack2(cv, cv);
            fma2(acc[i][0], c2, t0.x); fma2(acc[i][1], c2, t0.y);
            fma2(acc[i][2], c2, t1.x); fma2(acc[i][3], c2, t1.y);
        }
    }
    if (!xpath) {
        float* dst = g_Z + (size_t)slab * 16384u;
#pragma unroll
        for (int i = 0; i < 8; i++) {
            float* p = dst + (size_t)(n0 + i) * 64u + tx * 4;
            float2 a0 = unpk(acc[i][0]), a1 = unpk(acc[i][1]);
            float2 a2 = unpk(acc[i][2]), a3 = unpk(acc[i][3]);
            *(float4*)p        = make_float4(a0.x, a0.y, a1.x, a1.y);
            *(float4*)(p + 32) = make_float4(a2.x, a2.y, a3.x, a3.y);
        }
    } else {
        size_t base = (size_t)(slab >> 8) * 4194304u + (size_t)(slab & 255) * 64u;
#pragma unroll
        for (int i = 0; i < 8; i++) {
            float* p = g_Z + base + (size_t)(n0 + i) * 16384u + tx * 4;
            float4 v0 = *(float4*)p, v1 = *(float4*)(p + 32);
            float2 a0 = unpk(acc[i][0]), a1 = unpk(acc[i][1]);
            float2 a2 = unpk(acc[i][2]), a3 = unpk(acc[i][3]);
            v0.x += a0.x; v0.y += a0.y; v0.z += a1.x; v0.w += a1.y;
            v1.x += a2.x; v1.y += a2.y; v1.z += a3.x; v1.w += a3.y;
            *(float4*)p = v0; *(float4*)(p + 32) = v1;
        }
    }
}

// --------------------- FF via mma.sync bf16 split, ILP-restructured ----------
#define P1 72
#define P2 264
#define FFSM_B1 141312
#define FFSM_TOT 143104

__global__ __launch_bounds__(256) void k_ffW(
    const float* __restrict__ b1, const float* __restrict__ b2,
    const float* __restrict__ lg, const float* __restrict__ lb,
    float* __restrict__ out)
{
    extern __shared__ char smc[];
    u16* W1h = (u16*)smc;
    u16* W1l = W1h + 256 * P1;
    u16* W2h = W1l + 256 * P1;
    u16* W2l = W2h + 64 * P2;
    float* b1s = (float*)(smc + FFSM_B1);
    float* b2s = b1s + 256;
    float* gs  = b2s + 64;
    float* bsb = gs + 64;
    int t = threadIdx.x;

    for (int i = t; i < 16384; i += 256) {
        int j = i >> 6, c = i & 63;
        W1h[j * P1 + c] = g_W1s[i];
        W1l[j * P1 + c] = g_W1s[16384 + i];
        int o = i >> 8, j2 = i & 255;
        W2h[o * P2 + j2] = g_W2s[i];
        W2l[o * P2 + j2] = g_W2s[16384 + i];
    }
    b1s[t] = b1[t];
    if (t < 64) { b2s[t] = b2[t]; gs[t] = lg[t]; bsb[t] = lb[t]; }
    __syncthreads();

    int lane = t & 31, w = t >> 5;
    int g = lane >> 2, tg = lane & 3;

    for (int tile = blockIdx.x * 8; tile < blockIdx.x * 8 + 8; tile++) {
        size_t row0 = (size_t)tile * 128u + (size_t)w * 16u;

        // A-frags for GEMM1 from g_Z
        u32 zh[4][4], zl[4][4];
#pragma unroll
        for (int kt = 0; kt < 4; kt++) {
            const float* zr  = g_Z + (row0 + g) * 64u + kt * 16 + tg * 2;
            const float* zr8 = zr + 8 * 64;
            float2 p0 = *(const float2*)zr,  p2 = *(const float2*)(zr + 8);
            float2 p1 = *(const float2*)zr8, p3 = *(const float2*)(zr8 + 8);
            zh[kt][0] = bfsplit(p0.x, p0.y, zl[kt][0]);
            zh[kt][1] = bfsplit(p1.x, p1.y, zl[kt][1]);
            zh[kt][2] = bfsplit(p2.x, p2.y, zl[kt][2]);
            zh[kt][3] = bfsplit(p3.x, p3.y, zl[kt][3]);
        }

        float y[8][4] = {};
#pragma unroll
        for (int kt2 = 0; kt2 < 16; kt2++) {
            // ---- GEMM1: 6 independent accumulator chains (2 halves x 3 passes)
            float c[2][3][4] = {};
#pragma unroll
            for (int kt = 0; kt < 4; kt++) {
#pragma unroll
                for (int half = 0; half < 2; half++) {
                    int nt = kt2 * 2 + half;
                    const u16* wh = W1h + (nt * 8 + g) * P1 + tg * 2;
                    const u16* wl = W1l + (nt * 8 + g) * P1 + tg * 2;
                    u32 bh0 = *(const u32*)(wh + kt * 16);
                    u32 bh1 = *(const u32*)(wh + kt * 16 + 8);
                    u32 bl0 = *(const u32*)(wl + kt * 16);
                    u32 bl1 = *(const u32*)(wl + kt * 16 + 8);
                    mma16816(c[half][0], zh[kt], bh0, bh1);
                    mma16816(c[half][1], zl[kt], bh0, bh1);
                    mma16816(c[half][2], zh[kt], bl0, bl1);
                }
            }
            // combine + bias + relu + split -> GEMM2 A frags
            u32 aH[4], aL[4];
#pragma unroll
            for (int half = 0; half < 2; half++) {
                int nt = kt2 * 2 + half;
                float2 bv = *(const float2*)(b1s + nt * 8 + tg * 2);
                float h0 = fmaxf(c[half][0][0] + c[half][1][0] + c[half][2][0] + bv.x, 0.f);
                float h1 = fmaxf(c[half][0][1] + c[half][1][1] + c[half][2][1] + bv.y, 0.f);
                float h2 = fmaxf(c[half][0][2] + c[half][1][2] + c[half][2][2] + bv.x, 0.f);
                float h3 = fmaxf(c[half][0][3] + c[half][1][3] + c[half][2][3] + bv.y, 0.f);
                u32 l0, l1;
                aH[half * 2 + 0] = bfsplit(h0, h1, l0); aL[half * 2 + 0] = l0;
                aH[half * 2 + 1] = bfsplit(h2, h3, l1); aL[half * 2 + 1] = l1;
            }
            // ---- GEMM2: pass-outer, nt2-inner (distance-8 chains), bh cached
            u32 bh[8][2];
#pragma unroll
            for (int nt2 = 0; nt2 < 8; nt2++) {
                const u16* wh = W2h + (nt2 * 8 + g) * P2 + kt2 * 16 + tg * 2;
                bh[nt2][0] = *(const u32*)wh; bh[nt2][1] = *(const u32*)(wh + 8);
            }
#pragma unroll
            for (int nt2 = 0; nt2 < 8; nt2++) mma16816(y[nt2], aH, bh[nt2][0], bh[nt2][1]);
#pragma unroll
            for (int nt2 = 0; nt2 < 8; nt2++) mma16816(y[nt2], aL, bh[nt2][0], bh[nt2][1]);
#pragma unroll
            for (int nt2 = 0; nt2 < 8; nt2++) {
                const u16* wl = W2l + (nt2 * 8 + g) * P2 + kt2 * 16 + tg * 2;
                u32 bl0 = *(const u32*)wl, bl1 = *(const u32*)(wl + 8);
                mma16816(y[nt2], aH, bl0, bl1);
            }
        }

        // bias + LN partials
        float sg = 0.f, s2g = 0.f, sg8 = 0.f, s2g8 = 0.f;
#pragma unroll
        for (int nt2 = 0; nt2 < 8; nt2++) {
            float2 bv = *(const float2*)(b2s + nt2 * 8 + tg * 2);
            float v0 = y[nt2][0] + bv.x, v1 = y[nt2][1] + bv.y;
            float v2 = y[nt2][2] + bv.x, v3 = y[nt2][3] + bv.y;
            y[nt2][0] = v0; y[nt2][1] = v1; y[nt2][2] = v2; y[nt2][3] = v3;
            sg  += v0 + v1; s2g  += v0 * v0 + v1 * v1;
            sg8 += v2 + v3; s2g8 += v2 * v2 + v3 * v3;
        }
#pragma unroll
        for (int msk = 1; msk <= 2; msk <<= 1) {
            sg   += __shfl_xor_sync(0xFFFFFFFFu, sg,   msk);
            s2g  += __shfl_xor_sync(0xFFFFFFFFu, s2g,  msk);
            sg8  += __shfl_xor_sync(0xFFFFFFFFu, sg8,  msk);
            s2g8 += __shfl_xor_sync(0xFFFFFFFFu, s2g8, msk);
        }
        float mu  = sg  * 0.015625f, rs  = rsqrtf(s2g  * 0.015625f - mu  * mu  + 1e-5f);
        float mu8 = sg8 * 0.015625f, rs8 = rsqrtf(s2g8 * 0.015625f - mu8 * mu8 + 1e-5f);
        float* op  = out + (row0 + g) * 64u;
        float* op8 = op + 8 * 64;
#pragma unroll
        for (int nt2 = 0; nt2 < 8; nt2++) {
            int o0 = nt2 * 8 + tg * 2;
            float2 gv = *(const float2*)(gs + o0);
            float2 bb = *(const float2*)(bsb + o0);
            float2 r;
            r.x = (y[nt2][0] - mu) * rs * gv.x + bb.x;
            r.y = (y[nt2][1] - mu) * rs * gv.y + bb.y;
            *(float2*)(op + o0) = r;
            r.x = (y[nt2][2] - mu8) * rs8 * gv.x + bb.x;
            r.y = (y[nt2][3] - mu8) * rs8 * gv.y + bb.y;
            *(float2*)(op8 + o0) = r;
        }
    }
}

// ----------------------------- launch ---------------------------------------
extern "C" void kernel_launch(void* const* d_in, const int* in_sizes, int n_in,
                              void* d_out, int out_size) {
    (void)in_sizes; (void)n_in; (void)out_size;
    const float* x    = (const float*)d_in[0];
    const float* w1re = (const float*)d_in[1];
    const float* w1im = (const float*)d_in[2];
    const float* w2re = (const float*)d_in[3];
    const float* w2im = (const float*)d_in[4];
    const float* ffw1 = (const float*)d_in[5];
    const float* ffb1 = (const float*)d_in[6];
    const float* ffw2 = (const float*)d_in[7];
    const float* ffb2 = (const float*)d_in[8];
    const float* lng  = (const float*)d_in[9];
    const float* lnb  = (const float*)d_in[10];
    float* out = (float*)d_out;

    cudaFuncSetAttribute(k_fwd, cudaFuncAttributeMaxDynamicSharedMemorySize, 98304);
    cudaFuncSetAttribute(k_mix, cudaFuncAttributeMaxDynamicSharedMemorySize, 66560);
    cudaFuncSetAttribute(k_inv, cudaFuncAttributeMaxDynamicSharedMemorySize, 82944);
    cudaFuncSetAttribute(k_ffW, cudaFuncAttributeMaxDynamicSharedMemorySize, FFSM_TOT);

    k_basis<<<64, 256>>>();
    k_wt<<<512, 256>>>(w1re, w1im, w2re, w2im);
    k_prep<<<64, 256>>>(ffw1, ffw2);

    k_fwd<<<2048, 256, 98304>>>(x, 0);
    k_mix<<<dim3(64, 32), 256, 66560>>>(0);
    k_inv<<<4096, 256, 82944>>>(0);

    k_fwd<<<2048, 256, 98304>>>(x, 1);
    k_mix<<<dim3(64, 32), 256, 66560>>>(1);
    k_inv<<<4096, 256, 82944>>>(1);

    k_ffW<<<1024, 256, FFSM_TOT>>>(ffb1, ffb2, lng, lnb, out);
}

// round 15
// speedup vs baseline: 1.1915x; 1.1915x over previous
#include <cuda_runtime.h>
#include <math.h>

// B=16, M=N=256, C=OUT=64, modes=32/axis, FF_HID=256.
#define PI_D 3.14159265358979323846
typedef unsigned long long u64;

__device__ __forceinline__ u64 pack2(float lo, float hi) {
    u64 r; asm("mov.b64 %0,{%1,%2};" : "=l"(r) : "f"(lo), "f"(hi)); return r;
}
__device__ __forceinline__ float2 unpk(u64 v) {
    float2 f; asm("mov.b64 {%0,%1},%2;" : "=f"(f.x), "=f"(f.y) : "l"(v)); return f;
}
__device__ __forceinline__ void fma2(u64& d, u64 a, u64 b) {
    asm("fma.rn.f32x2 %0,%1,%2,%0;" : "+l"(d) : "l"(a), "l"(b));
}

// ----------------------------- device scratch ------------------------------
__device__ float g_Ft [256 * 64];            // forward DFT [n][kr]
__device__ float g_Cit[256 * 64];            // inverse DFT [n][kr]
__device__ float g_w1t[2 * 32 * 64 * 64];    // [re|im][k][c][o]
__device__ float g_w2t[2 * 32 * 64 * 64];
__device__ float g_S[(size_t)4096 * 4096];   // spectra [slab][kr][c]
__device__ float g_T[(size_t)4096 * 4096];   // mixed   [slab][kr][o]
__device__ float g_Z[(size_t)1048576 * 64];  // xx+xy   [b][m][n][o]

// ----------------------------- basis ---------------------------------------
__global__ void k_basis() {
    int idx = blockIdx.x * 256 + threadIdx.x;
    if (idx >= 16384) return;
    int n = idx >> 6, kr = idx & 63, k = kr >> 1;
    double th = 2.0 * PI_D * (double)k * (double)n / 256.0;
    double c = cos(th), s = sin(th);
    g_Ft[idx] = (float)(((kr & 1) ? -s : c) * 0.0625);
    double v;
    if (k == 0) v = (kr & 1) ? 0.0 : 0.0625;
    else        v = ((kr & 1) ? -2.0 * s : 2.0 * c) * 0.0625;
    g_Cit[idx] = (float)v;
}

// --------------------- weight transpose [c][o][k] -> [k][c][o] --------------
__global__ void k_wt(const float* __restrict__ w1re, const float* __restrict__ w1im,
                     const float* __restrict__ w2re, const float* __restrict__ w2im) {
    int idx = blockIdx.x * 256 + threadIdx.x;
    if (idx >= 131072) return;
    int k = idx >> 12, c = (idx >> 6) & 63, o = idx & 63;
    int src = (c * 64 + o) * 32 + k;
    g_w1t[idx]          = w1re[src];
    g_w1t[131072 + idx] = w1im[src];
    g_w2t[idx]          = w2re[src];
    g_w2t[131072 + idx] = w2im[src];
}

// --------------------- forward DFT GEMM, 4 n-chunks (48KB smem) -------------
// S[slab][kr][c] = sum_n Ft[n][kr] * x[slab][n][c]. 2 slabs/block.
__global__ __launch_bounds__(256) void k_fwd(const float* __restrict__ x, int xpath) {
    extern __shared__ float sm[];
    float* fs = sm;           // [64][64]
    float* xs = sm + 4096;    // [2][64][64]
    int t = threadIdx.x;
    int sl = t >> 7, s = t & 127;
    int tx = s & 15, ty = s >> 4;   // c-group 16x4, kr-group 8x8
    int slab0 = blockIdx.x * 2;

    u64 acc[4][4] = {};  // [kr-pair][c]

    for (int h = 0; h < 4; h++) {
        for (int i = t; i < 1024; i += 256)
            ((float4*)fs)[i] = ((const float4*)g_Ft)[h * 1024 + i];
        if (!xpath) {
            for (int i = t; i < 2048; i += 256) {
                int ssl = i >> 10, j = i & 1023;
                ((float4*)xs)[i] =
                    ((const float4*)x)[(size_t)(slab0 + ssl) * 4096u + (size_t)h * 1024u + j];
            }
        } else {
            for (int i = t; i < 2048; i += 256) {
                int ssl = i >> 10, j = i & 1023;
                int mm = h * 64 + (j >> 4), c4 = (j & 15) * 4;
                int slab = slab0 + ssl;
                size_t base = (size_t)(slab >> 8) * 4194304u + (size_t)(slab & 255) * 64u;
                ((float4*)xs)[i] = *(const float4*)(x + base + (size_t)mm * 16384u + c4);
            }
        }
        __syncthreads();

        const float* fb = fs + ty * 8;
        const float* xb = xs + sl * 4096 + tx * 4;
#pragma unroll 4
        for (int n = 0; n < 64; n++) {
            u64 f0 = *(const u64*)(fb + n * 64 + 0);
            u64 f1 = *(const u64*)(fb + n * 64 + 2);
            u64 f2 = *(const u64*)(fb + n * 64 + 4);
            u64 f3 = *(const u64*)(fb + n * 64 + 6);
            float4 xv = *(const float4*)(xb + n * 64);
            u64 x0 = pack2(xv.x, xv.x), x1 = pack2(xv.y, xv.y);
            u64 x2 = pack2(xv.z, xv.z), x3 = pack2(xv.w, xv.w);
            fma2(acc[0][0], f0, x0); fma2(acc[0][1], f0, x1);
            fma2(acc[0][2], f0, x2); fma2(acc[0][3], f0, x3);
            fma2(acc[1][0], f1, x0); fma2(acc[1][1], f1, x1);
            fma2(acc[1][2], f1, x2); fma2(acc[1][3], f1, x3);
            fma2(acc[2][0], f2, x0); fma2(acc[2][1], f2, x1);
            fma2(acc[2][2], f2, x2); fma2(acc[2][3], f2, x3);
            fma2(acc[3][0], f3, x0); fma2(acc[3][1], f3, x1);
            fma2(acc[3][2], f3, x2); fma2(acc[3][3], f3, x3);
        }
        __syncthreads();
    }

    float* Sp = g_S + (size_t)(slab0 + sl) * 4096u + (size_t)(ty * 8) * 64u + tx * 4;
#pragma unroll
    for (int p = 0; p < 4; p++) {
        float2 a0 = unpk(acc[p][0]), a1 = unpk(acc[p][1]);
        float2 a2 = unpk(acc[p][2]), a3 = unpk(acc[p][3]);
        *(float4*)(Sp + (2 * p) * 64)     = make_float4(a0.x, a1.x, a2.x, a3.x);
        *(float4*)(Sp + (2 * p + 1) * 64) = make_float4(a0.y, a1.y, a2.y, a3.y);
    }
}

// --------------------- per-mode complex mix (unchanged R4) ------------------
__global__ __launch_bounds__(256) void k_mix(int which) {
    extern __shared__ float sm[];
    float* Ss  = sm;             // [64 slabs][132]
    float* Wre = sm + 64 * 132;  // [64c][64o]
    float* Wim = Wre + 4096;
    const float* wt = which ? g_w2t : g_w1t;
    int t = threadIdx.x;
    int k = blockIdx.y;
    int s0 = blockIdx.x * 64;
    for (int i = t; i < 2048; i += 256) {
        int s = i >> 5, q = (i & 31) * 4;
        float4 v = *(const float4*)(g_S + (size_t)(s0 + s) * 4096u + (size_t)k * 128u + q);
        *(float4*)(Ss + s * 132 + q) = v;
    }
    for (int i = t; i < 1024; i += 256) {
        ((float4*)Wre)[i] = *(const float4*)(wt + (size_t)k * 4096u + i * 4);
        ((float4*)Wim)[i] = *(const float4*)(wt + 131072u + (size_t)k * 4096u + i * 4);
    }
    __syncthreads();
    int tx = t & 15, ty = t >> 4;
    u64 ar[4][2] = {}, ai[4][2] = {};
#pragma unroll 4
    for (int c = 0; c < 64; c++) {
        ulonglong2 wr = *(const ulonglong2*)(Wre + c * 64 + tx * 4);
        ulonglong2 wi = *(const ulonglong2*)(Wim + c * 64 + tx * 4);
#pragma unroll
        for (int i = 0; i < 4; i++) {
            float srv = Ss[(ty * 4 + i) * 132 + c];
            float siv = Ss[(ty * 4 + i) * 132 + 64 + c];
            u64 sr2 = pack2(srv, srv), si2 = pack2(siv, siv), ns2 = pack2(-siv, -siv);
            fma2(ar[i][0], sr2, wr.x); fma2(ar[i][0], ns2, wi.x);
            fma2(ar[i][1], sr2, wr.y); fma2(ar[i][1], ns2, wi.y);
            fma2(ai[i][0], sr2, wi.x); fma2(ai[i][0], si2, wr.x);
            fma2(ai[i][1], sr2, wi.y); fma2(ai[i][1], si2, wr.y);
        }
    }
#pragma unroll
    for (int i = 0; i < 4; i++) {
        float* Tp = g_T + (size_t)(s0 + ty * 4 + i) * 4096u + (size_t)(2 * k) * 64u + tx * 4;
        float2 r0 = unpk(ar[i][0]), r1 = unpk(ar[i][1]);
        float2 m0 = unpk(ai[i][0]), m1 = unpk(ai[i][1]);
        *(float4*)Tp        = make_float4(r0.x, r0.y, r1.x, r1.y);
        *(float4*)(Tp + 64) = make_float4(m0.x, m0.y, m1.x, m1.y);
    }
}

// --------------------- inverse DFT GEMM, 2 n-chunks (49KB smem) -------------
// y[n][o] = sum_kr Cit[n][kr] * T[slab][kr][o]. 4 rows/thread/chunk.
__global__ __launch_bounds__(256) void k_inv(int xpath) {
    extern __shared__ float sm[];
    float* Ts = sm;           // [64][64]
    float* Cs = sm + 4096;    // [128][65]
    int t = threadIdx.x;
    int slab = blockIdx.x;

    {
        const float4* tsrc = (const float4*)(g_T + (size_t)slab * 4096u);
        for (int i = t; i < 1024; i += 256) ((float4*)Ts)[i] = tsrc[i];
    }
    int tx = t & 7, ty = t >> 3;   // 8 o-groups x 32 n-groups
    size_t xbase = (size_t)(slab >> 8) * 4194304u + (size_t)(slab & 255) * 64u;

    for (int ch = 0; ch < 2; ch++) {
        for (int i = t; i < 8192; i += 256)
            Cs[(i >> 6) * 65 + (i & 63)] = g_Cit[ch * 8192 + i];
        __syncthreads();

        int n0 = ty * 4;
        u64 acc[4][4] = {};
#pragma unroll 2
        for (int kr = 0; kr < 64; kr++) {
            ulonglong2 t0 = *(const ulonglong2*)(Ts + kr * 64 + tx * 4);
            ulonglong2 t1 = *(const ulonglong2*)(Ts + kr * 64 + 32 + tx * 4);
#pragma unroll
            for (int i = 0; i < 4; i++) {
                float cv = Cs[(n0 + i) * 65 + kr];
                u64 c2 = pack2(cv, cv);
                fma2(acc[i][0], c2, t0.x); fma2(acc[i][1], c2, t0.y);
                fma2(acc[i][2], c2, t1.x); fma2(acc[i][3], c2, t1.y);
            }
        }

        int nb = ch * 128 + n0;
        if (!xpath) {
            float* dst = g_Z + (size_t)slab * 16384u;
#pragma unroll
            for (int i = 0; i < 4; i++) {
                float* p = dst + (size_t)(nb + i) * 64u + tx * 4;
                float2 a0 = unpk(acc[i][0]), a1 = unpk(acc[i][1]);
                float2 a2 = unpk(acc[i][2]), a3 = unpk(acc[i][3]);
                *(float4*)p        = make_float4(a0.x, a0.y, a1.x, a1.y);
                *(float4*)(p + 32) = make_float4(a2.x, a2.y, a3.x, a3.y);
            }
        } else {
#pragma unroll
            for (int i = 0; i < 4; i++) {
                float* p = g_Z + xbase + (size_t)(nb + i) * 16384u + tx * 4;
                float4 v0 = *(float4*)p, v1 = *(float4*)(p + 32);
                float2 a0 = unpk(acc[i][0]), a1 = unpk(acc[i][1]);
                float2 a2 = unpk(acc[i][2]), a3 = unpk(acc[i][3]);
                v0.x += a0.x; v0.y += a0.y; v0.z += a1.x; v0.w += a1.y;
                v1.x += a2.x; v1.y += a2.y; v1.z += a3.x; v1.w += a3.y;
                *(float4*)p = v0; *(float4*)(p + 32) = v1;
            }
        }
        __syncthreads();
    }
}

// --------------------- fused FeedForward + LayerNorm (R4, proven) -----------
__global__ __launch_bounds__(256) void k_ff(
    const float* __restrict__ w1, const float* __restrict__ b1,
    const float* __restrict__ w2, const float* __restrict__ b2,
    const float* __restrict__ lg, const float* __restrict__ lb,
    float* __restrict__ out)
{
    extern __shared__ float sm[];
    float* W1s = sm;                 // [64][256]
    float* W2s = W1s + 16384;        // [256][64]
    float* Zs  = W2s + 16384;        // [64][68]
    float* Hs  = Zs + 4352;          // [64][260]
    float* b1s = Hs + 16640;
    float* b2s = b1s + 256;
    float* gs  = b2s + 64;
    float* bs  = gs + 64;
    float* mus = bs + 64;
    float* rss = mus + 64;
    float* Pp  = W1s;                // partials overlay
    int t = threadIdx.x;

    for (int i = t; i < 4096; i += 256) {
        ((float4*)W1s)[i] = ((const float4*)w1)[i];
        ((float4*)W2s)[i] = ((const float4*)w2)[i];
    }
    b1s[t] = b1[t];
    if (t < 64) { b2s[t] = b2[t]; gs[t] = lg[t]; bs[t] = lb[t]; }

    size_t r0 = (size_t)blockIdx.x * 64u;
    {
        const float4* zsrc = (const float4*)(g_Z + r0 * 64u);
        for (int i = t; i < 1024; i += 256) {
            int row = i >> 4, c4 = (i & 15) * 4;
            *(float4*)(Zs + row * 68 + c4) = zsrc[i];
        }
    }
    __syncthreads();

    // ---- stage 1: H = relu(Z @ W1 + b1), 8x8 per thread --------------------
    {
        int txs = t & 31, tys = t >> 5;
        u64 acc[8][4];
        {
            ulonglong2 bA = *(const ulonglong2*)(b1s + txs * 4);
            ulonglong2 bB = *(const ulonglong2*)(b1s + 128 + txs * 4);
#pragma unroll
            for (int i = 0; i < 8; i++) {
                acc[i][0] = bA.x; acc[i][1] = bA.y;
                acc[i][2] = bB.x; acc[i][3] = bB.y;
            }
        }
        const float* zb = Zs + tys * 8 * 68;
#pragma unroll 4
        for (int c = 0; c < 64; c++) {
            ulonglong2 wA = *(const ulonglong2*)(W1s + c * 256 + txs * 4);
            ulonglong2 wB = *(const ulonglong2*)(W1s + c * 256 + 128 + txs * 4);
#pragma unroll
            for (int i = 0; i < 8; i++) {
                float z = zb[i * 68 + c];
                u64 z2 = pack2(z, z);
                fma2(acc[i][0], z2, wA.x); fma2(acc[i][1], z2, wA.y);
                fma2(acc[i][2], z2, wB.x); fma2(acc[i][3], z2, wB.y);
            }
        }
#pragma unroll
        for (int i = 0; i < 8; i++) {
            float* hp = Hs + (tys * 8 + i) * 260;
            float2 a0 = unpk(acc[i][0]), a1 = unpk(acc[i][1]);
            float2 a2 = unpk(acc[i][2]), a3 = unpk(acc[i][3]);
            *(float4*)(hp + txs * 4) = make_float4(
                fmaxf(a0.x, 0.f), fmaxf(a0.y, 0.f), fmaxf(a1.x, 0.f), fmaxf(a1.y, 0.f));
            *(float4*)(hp + 128 + txs * 4) = make_float4(
                fmaxf(a2.x, 0.f), fmaxf(a2.y, 0.f), fmaxf(a3.x, 0.f), fmaxf(a3.y, 0.f));
        }
    }
    __syncthreads();

    // ---- stage 2: Y = H @ W2 + b2, 8x8 tiles, 4-way k-split + reduce -------
    int rg = t & 7, og = (t >> 3) & 7, q = t >> 6;
    u64 acc[8][4] = {};
    {
        int j0 = q * 64;
#pragma unroll 4
        for (int jj = 0; jj < 64; jj++) {
            int j = j0 + jj;
            ulonglong2 wA = *(const ulonglong2*)(W2s + j * 64 + og * 4);
            ulonglong2 wB = *(const ulonglong2*)(W2s + j * 64 + 32 + og * 4);
#pragma unroll
            for (int i = 0; i < 8; i++) {
                float h = Hs[(rg + 8 * i) * 260 + j];
                u64 h2 = pack2(h, h);
                fma2(acc[i][0], h2, wA.x); fma2(acc[i][1], h2, wA.y);
                fma2(acc[i][2], h2, wB.x); fma2(acc[i][3], h2, wB.y);
            }
        }
        if (q) {
            float* P = Pp + (q - 1) * 4352;
#pragma unroll
            for (int i = 0; i < 8; i++) {
                int row = rg + 8 * i;
                float2 a0 = unpk(acc[i][0]), a1 = unpk(acc[i][1]);
                float2 a2 = unpk(acc[i][2]), a3 = unpk(acc[i][3]);
                *(float4*)(P + row * 68 + og * 4)      = make_float4(a0.x, a0.y, a1.x, a1.y);
                *(float4*)(P + row * 68 + 32 + og * 4) = make_float4(a2.x, a2.y, a3.x, a3.y);
            }
        }
    }
    __syncthreads();

    if (q == 0) {
        float4 bv0 = *(const float4*)(b2s + og * 4);
        float4 bv1 = *(const float4*)(b2s + 32 + og * 4);
#pragma unroll
        for (int i = 0; i < 8; i++) {
            int row = rg + 8 * i;
            float2 a0 = unpk(acc[i][0]), a1 = unpk(acc[i][1]);
            float2 a2 = unpk(acc[i][2]), a3 = unpk(acc[i][3]);
            float4 v0 = make_float4(a0.x + bv0.x, a0.y + bv0.y, a1.x + bv0.z, a1.y + bv0.w);
            float4 v1 = make_float4(a2.x + bv1.x, a2.y + bv1.y, a3.x + bv1.z, a3.y + bv1.w);
#pragma unroll
            for (int s = 0; s < 3; s++) {
                float4 p0 = *(const float4*)(Pp + s * 4352 + row * 68 + og * 4);
                float4 p1 = *(const float4*)(Pp + s * 4352 + row * 68 + 32 + og * 4);
                v0.x += p0.x; v0.y += p0.y; v0.z += p0.z; v0.w += p0.w;
                v1.x += p1.x; v1.y += p1.y; v1.z += p1.z; v1.w += p1.w;
            }
            *(float4*)(Zs + row * 68 + og * 4)      = v0;
            *(float4*)(Zs + row * 68 + 32 + og * 4) = v1;
        }
    }
    __syncthreads();

    if (t < 64) {
        const float* y = Zs + t * 68;
        float s = 0.f, s2 = 0.f;
#pragma unroll 8
        for (int c = 0; c < 64; c++) { float v = y[c]; s += v; s2 += v * v; }
        float mu = s * 0.015625f;
        float var = s2 * 0.015625f - mu * mu;
        mus[t] = mu; rss[t] = rsqrtf(var + 1e-5f);
    }
    __syncthreads();

    {
        int row = t >> 2, cg = (t & 3) * 16;
        float mu = mus[row], rs = rss[row];
        const float* y = Zs + row * 68;
        float* op = out + (r0 + (size_t)row) * 64u;
#pragma unroll
        for (int kk = 0; kk < 4; kk++) {
            int c = cg + kk * 4;
            float4 v = *(const float4*)(y + c);
            float4 o;
            o.x = (v.x - mu) * rs * gs[c + 0] + bs[c + 0];
            o.y = (v.y - mu) * rs * gs[c + 1] + bs[c + 1];
            o.z = (v.z - mu) * rs * gs[c + 2] + bs[c + 2];
            o.w = (v.w - mu) * rs * gs[c + 3] + bs[c + 3];
            *(float4*)(op + c) = o;
        }
    }
}

// ----------------------------- launch ---------------------------------------
extern "C" void kernel_launch(void* const* d_in, const int* in_sizes, int n_in,
                              void* d_out, int out_size) {
    (void)in_sizes; (void)n_in; (void)out_size;
    const float* x    = (const float*)d_in[0];
    const float* w1re = (const float*)d_in[1];
    const float* w1im = (const float*)d_in[2];
    const float* w2re = (const float*)d_in[3];
    const float* w2im = (const float*)d_in[4];
    const float* ffw1 = (const float*)d_in[5];
    const float* ffb1 = (const float*)d_in[6];
    const float* ffw2 = (const float*)d_in[7];
    const float* ffb2 = (const float*)d_in[8];
    const float* lng  = (const float*)d_in[9];
    const float* lnb  = (const float*)d_in[10];
    float* out = (float*)d_out;

    cudaFuncSetAttribute(k_fwd, cudaFuncAttributeMaxDynamicSharedMemorySize, 49152);
    cudaFuncSetAttribute(k_mix, cudaFuncAttributeMaxDynamicSharedMemorySize, 66560);
    cudaFuncSetAttribute(k_inv, cudaFuncAttributeMaxDynamicSharedMemorySize, 49664);
    cudaFuncSetAttribute(k_ff,  cudaFuncAttributeMaxDynamicSharedMemorySize, 217344);

    k_basis<<<64, 256>>>();
    k_wt<<<512, 256>>>(w1re, w1im, w2re, w2im);

    // y-path
    k_fwd<<<2048, 256, 49152>>>(x, 0);
    k_mix<<<dim3(64, 32), 256, 66560>>>(0);
    k_inv<<<4096, 256, 49664>>>(0);

    // x-path (accumulates into Z)
    k_fwd<<<2048, 256, 49152>>>(x, 1);
    k_mix<<<dim3(64, 32), 256, 66560>>>(1);
    k_inv<<<4096, 256, 49664>>>(1);

    k_ff<<<16384, 256, 217344>>>(ffw1, ffb1, ffw2, ffb2, lng, lnb, out);
}

// round 16
// speedup vs baseline: 1.2500x; 1.0491x over previous
#include <cuda_runtime.h>
#include <math.h>

// B=16, M=N=256, C=OUT=64, modes=32/axis, FF_HID=256.
#define PI_D 3.14159265358979323846
typedef unsigned long long u64;

__device__ __forceinline__ u64 pack2(float lo, float hi) {
    u64 r; asm("mov.b64 %0,{%1,%2};" : "=l"(r) : "f"(lo), "f"(hi)); return r;
}
__device__ __forceinline__ float2 unpk(u64 v) {
    float2 f; asm("mov.b64 {%0,%1},%2;" : "=f"(f.x), "=f"(f.y) : "l"(v)); return f;
}
__device__ __forceinline__ void fma2(u64& d, u64 a, u64 b) {
    asm("fma.rn.f32x2 %0,%1,%2,%0;" : "+l"(d) : "l"(a), "l"(b));
}

// ----------------------------- device scratch ------------------------------
__device__ float g_Ft [256 * 64];
__device__ float g_Cit[256 * 64];
__device__ float g_w1t[2 * 32 * 64 * 64];
__device__ float g_w2t[2 * 32 * 64 * 64];
__device__ float g_S[(size_t)4096 * 4096];
__device__ float g_T[(size_t)4096 * 4096];
__device__ float g_Z[(size_t)1048576 * 64];

// ----------------------------- basis ---------------------------------------
__global__ void k_basis() {
    int idx = blockIdx.x * 256 + threadIdx.x;
    if (idx >= 16384) return;
    int n = idx >> 6, kr = idx & 63, k = kr >> 1;
    double th = 2.0 * PI_D * (double)k * (double)n / 256.0;
    double c = cos(th), s = sin(th);
    g_Ft[idx] = (float)(((kr & 1) ? -s : c) * 0.0625);
    double v;
    if (k == 0) v = (kr & 1) ? 0.0 : 0.0625;
    else        v = ((kr & 1) ? -2.0 * s : 2.0 * c) * 0.0625;
    g_Cit[idx] = (float)v;
}

__global__ void k_wt(const float* __restrict__ w1re, const float* __restrict__ w1im,
                     const float* __restrict__ w2re, const float* __restrict__ w2im) {
    int idx = blockIdx.x * 256 + threadIdx.x;
    if (idx >= 131072) return;
    int k = idx >> 12, c = (idx >> 6) & 63, o = idx & 63;
    int src = (c * 64 + o) * 32 + k;
    g_w1t[idx]          = w1re[src];
    g_w1t[131072 + idx] = w1im[src];
    g_w2t[idx]          = w2re[src];
    g_w2t[131072 + idx] = w2im[src];
}

// --------------------- forward DFT GEMM (R15) -------------------------------
__global__ __launch_bounds__(256) void k_fwd(const float* __restrict__ x, int xpath) {
    extern __shared__ float sm[];
    float* fs = sm;
    float* xs = sm + 4096;
    int t = threadIdx.x;
    int sl = t >> 7, s = t & 127;
    int tx = s & 15, ty = s >> 4;
    int slab0 = blockIdx.x * 2;
    u64 acc[4][4] = {};
    for (int h = 0; h < 4; h++) {
        for (int i = t; i < 1024; i += 256)
            ((float4*)fs)[i] = ((const float4*)g_Ft)[h * 1024 + i];
        if (!xpath) {
            for (int i = t; i < 2048; i += 256) {
                int ssl = i >> 10, j = i & 1023;
                ((float4*)xs)[i] =
                    ((const float4*)x)[(size_t)(slab0 + ssl) * 4096u + (size_t)h * 1024u + j];
            }
        } else {
            for (int i = t; i < 2048; i += 256) {
                int ssl = i >> 10, j = i & 1023;
                int mm = h * 64 + (j >> 4), c4 = (j & 15) * 4;
                int slab = slab0 + ssl;
                size_t base = (size_t)(slab >> 8) * 4194304u + (size_t)(slab & 255) * 64u;
                ((float4*)xs)[i] = *(const float4*)(x + base + (size_t)mm * 16384u + c4);
            }
        }
        __syncthreads();
        const float* fb = fs + ty * 8;
        const float* xb = xs + sl * 4096 + tx * 4;
#pragma unroll 4
        for (int n = 0; n < 64; n++) {
            u64 f0 = *(const u64*)(fb + n * 64 + 0);
            u64 f1 = *(const u64*)(fb + n * 64 + 2);
            u64 f2 = *(const u64*)(fb + n * 64 + 4);
            u64 f3 = *(const u64*)(fb + n * 64 + 6);
            float4 xv = *(const float4*)(xb + n * 64);
            u64 x0 = pack2(xv.x, xv.x), x1 = pack2(xv.y, xv.y);
            u64 x2 = pack2(xv.z, xv.z), x3 = pack2(xv.w, xv.w);
            fma2(acc[0][0], f0, x0); fma2(acc[0][1], f0, x1);
            fma2(acc[0][2], f0, x2); fma2(acc[0][3], f0, x3);
            fma2(acc[1][0], f1, x0); fma2(acc[1][1], f1, x1);
            fma2(acc[1][2], f1, x2); fma2(acc[1][3], f1, x3);
            fma2(acc[2][0], f2, x0); fma2(acc[2][1], f2, x1);
            fma2(acc[2][2], f2, x2); fma2(acc[2][3], f2, x3);
            fma2(acc[3][0], f3, x0); fma2(acc[3][1], f3, x1);
            fma2(acc[3][2], f3, x2); fma2(acc[3][3], f3, x3);
        }
        __syncthreads();
    }
    float* Sp = g_S + (size_t)(slab0 + sl) * 4096u + (size_t)(ty * 8) * 64u + tx * 4;
#pragma unroll
    for (int p = 0; p < 4; p++) {
        float2 a0 = unpk(acc[p][0]), a1 = unpk(acc[p][1]);
        float2 a2 = unpk(acc[p][2]), a3 = unpk(acc[p][3]);
        *(float4*)(Sp + (2 * p) * 64)     = make_float4(a0.x, a1.x, a2.x, a3.x);
        *(float4*)(Sp + (2 * p + 1) * 64) = make_float4(a0.y, a1.y, a2.y, a3.y);
    }
}

// --------------------- per-mode complex mix (R4) ----------------------------
__global__ __launch_bounds__(256) void k_mix(int which) {
    extern __shared__ float sm[];
    float* Ss  = sm;
    float* Wre = sm + 64 * 132;
    float* Wim = Wre + 4096;
    const float* wt = which ? g_w2t : g_w1t;
    int t = threadIdx.x;
    int k = blockIdx.y;
    int s0 = blockIdx.x * 64;
    for (int i = t; i < 2048; i += 256) {
        int s = i >> 5, q = (i & 31) * 4;
        float4 v = *(const float4*)(g_S + (size_t)(s0 + s) * 4096u + (size_t)k * 128u + q);
        *(float4*)(Ss + s * 132 + q) = v;
    }
    for (int i = t; i < 1024; i += 256) {
        ((float4*)Wre)[i] = *(const float4*)(wt + (size_t)k * 4096u + i * 4);
        ((float4*)Wim)[i] = *(const float4*)(wt + 131072u + (size_t)k * 4096u + i * 4);
    }
    __syncthreads();
    int tx = t & 15, ty = t >> 4;
    u64 ar[4][2] = {}, ai[4][2] = {};
#pragma unroll 4
    for (int c = 0; c < 64; c++) {
        ulonglong2 wr = *(const ulonglong2*)(Wre + c * 64 + tx * 4);
        ulonglong2 wi = *(const ulonglong2*)(Wim + c * 64 + tx * 4);
#pragma unroll
        for (int i = 0; i < 4; i++) {
            float srv = Ss[(ty * 4 + i) * 132 + c];
            float siv = Ss[(ty * 4 + i) * 132 + 64 + c];
            u64 sr2 = pack2(srv, srv), si2 = pack2(siv, siv), ns2 = pack2(-siv, -siv);
            fma2(ar[i][0], sr2, wr.x); fma2(ar[i][0], ns2, wi.x);
            fma2(ar[i][1], sr2, wr.y); fma2(ar[i][1], ns2, wi.y);
            fma2(ai[i][0], sr2, wi.x); fma2(ai[i][0], si2, wr.x);
            fma2(ai[i][1], sr2, wi.y); fma2(ai[i][1], si2, wr.y);
        }
    }
#pragma unroll
    for (int i = 0; i < 4; i++) {
        float* Tp = g_T + (size_t)(s0 + ty * 4 + i) * 4096u + (size_t)(2 * k) * 64u + tx * 4;
        float2 r0 = unpk(ar[i][0]), r1 = unpk(ar[i][1]);
        float2 m0 = unpk(ai[i][0]), m1 = unpk(ai[i][1]);
        *(float4*)Tp        = make_float4(r0.x, r0.y, r1.x, r1.y);
        *(float4*)(Tp + 64) = make_float4(m0.x, m0.y, m1.x, m1.y);
    }
}

// --------------------- inverse DFT GEMM (R15) -------------------------------
__global__ __launch_bounds__(256) void k_inv(int xpath) {
    extern __shared__ float sm[];
    float* Ts = sm;
    float* Cs = sm + 4096;
    int t = threadIdx.x;
    int slab = blockIdx.x;
    {
        const float4* tsrc = (const float4*)(g_T + (size_t)slab * 4096u);
        for (int i = t; i < 1024; i += 256) ((float4*)Ts)[i] = tsrc[i];
    }
    int tx = t & 7, ty = t >> 3;
    size_t xbase = (size_t)(slab >> 8) * 4194304u + (size_t)(slab & 255) * 64u;

    for (int ch = 0; ch < 2; ch++) {
        for (int i = t; i < 8192; i += 256)
            Cs[(i >> 6) * 65 + (i & 63)] = g_Cit[ch * 8192 + i];
        __syncthreads();
        int n0 = ty * 4;
        u64 acc[4][4] = {};
#pragma unroll 2
        for (int kr = 0; kr < 64; kr++) {
            ulonglong2 t0 = *(const ulonglong2*)(Ts + kr * 64 + tx * 4);
            ulonglong2 t1 = *(const ulonglong2*)(Ts + kr * 64 + 32 + tx * 4);
#pragma unroll
            for (int i = 0; i < 4; i++) {
                float cv = Cs[(n0 + i) * 65 + kr];
                u64 c2 = pack2(cv, cv);
                fma2(acc[i][0], c2, t0.x); fma2(acc[i][1], c2, t0.y);
                fma2(acc[i][2], c2, t1.x); fma2(acc[i][3], c2, t1.y);
            }
        }
        int nb = ch * 128 + n0;
        if (!xpath) {
            float* dst = g_Z + (size_t)slab * 16384u;
#pragma unroll
            for (int i = 0; i < 4; i++) {
                float* p = dst + (size_t)(nb + i) * 64u + tx * 4;
                float2 a0 = unpk(acc[i][0]), a1 = unpk(acc[i][1]);
                float2 a2 = unpk(acc[i][2]), a3 = unpk(acc[i][3]);
                *(float4*)p        = make_float4(a0.x, a0.y, a1.x, a1.y);
                *(float4*)(p + 32) = make_float4(a2.x, a2.y, a3.x, a3.y);
            }
        } else {
#pragma unroll
            for (int i = 0; i < 4; i++) {
                float* p = g_Z + xbase + (size_t)(nb + i) * 16384u + tx * 4;
                float4 v0 = *(float4*)p, v1 = *(float4*)(p + 32);
                float2 a0 = unpk(acc[i][0]), a1 = unpk(acc[i][1]);
                float2 a2 = unpk(acc[i][2]), a3 = unpk(acc[i][3]);
                v0.x += a0.x; v0.y += a0.y; v0.z += a1.x; v0.w += a1.y;
                v1.x += a2.x; v1.y += a2.y; v1.z += a3.x; v1.w += a3.y;
                *(float4*)p = v0; *(float4*)(p + 32) = v1;
            }
        }
        __syncthreads();
    }
}

// --------------------- FF + LayerNorm, 8 row-groups per block ----------------
// Weights staged ONCE per block; partials overlay Zs with serialized add.
__global__ __launch_bounds__(256) void k_ff(
    const float* __restrict__ w1, const float* __restrict__ b1,
    const float* __restrict__ w2, const float* __restrict__ b2,
    const float* __restrict__ lg, const float* __restrict__ lb,
    float* __restrict__ out)
{
    extern __shared__ float sm[];
    float* W1s = sm;                 // [64][256]
    float* W2s = W1s + 16384;        // [256][64]
    float* Zs  = W2s + 16384;        // [64][68]  (z, then partials P, then y)
    float* Hs  = Zs + 4352;          // [64][260]
    float* b1s = Hs + 16640;
    float* b2s = b1s + 256;
    float* gs  = b2s + 64;
    float* bs  = gs + 64;
    float* mus = bs + 64;
    float* rss = mus + 64;
    int t = threadIdx.x;

    for (int i = t; i < 4096; i += 256) {
        ((float4*)W1s)[i] = ((const float4*)w1)[i];
        ((float4*)W2s)[i] = ((const float4*)w2)[i];
    }
    b1s[t] = b1[t];
    if (t < 64) { b2s[t] = b2[t]; gs[t] = lg[t]; bs[t] = lb[t]; }
    __syncthreads();

    int txs = t & 31, tys = t >> 5;
    int rg = t & 7, og = (t >> 3) & 7, q = t >> 6;

    for (int g = 0; g < 8; g++) {
        size_t r0 = (size_t)blockIdx.x * 512u + (size_t)g * 64u;

        // ---- load z tile ---------------------------------------------------
        {
            const float4* zsrc = (const float4*)(g_Z + r0 * 64u);
            for (int i = t; i < 1024; i += 256) {
                int row = i >> 4, c4 = (i & 15) * 4;
                *(float4*)(Zs + row * 68 + c4) = zsrc[i];
            }
        }
        __syncthreads();

        // ---- stage 1: H = relu(Z @ W1 + b1), 8x8 per thread ----------------
        {
            u64 acc[8][4];
            {
                ulonglong2 bA = *(const ulonglong2*)(b1s + txs * 4);
                ulonglong2 bB = *(const ulonglong2*)(b1s + 128 + txs * 4);
#pragma unroll
                for (int i = 0; i < 8; i++) {
                    acc[i][0] = bA.x; acc[i][1] = bA.y;
                    acc[i][2] = bB.x; acc[i][3] = bB.y;
                }
            }
            const float* zb = Zs + tys * 8 * 68;
#pragma unroll 4
            for (int c = 0; c < 64; c++) {
                ulonglong2 wA = *(const ulonglong2*)(W1s + c * 256 + txs * 4);
                ulonglong2 wB = *(const ulonglong2*)(W1s + c * 256 + 128 + txs * 4);
#pragma unroll
                for (int i = 0; i < 8; i++) {
                    float z = zb[i * 68 + c];
                    u64 z2 = pack2(z, z);
                    fma2(acc[i][0], z2, wA.x); fma2(acc[i][1], z2, wA.y);
                    fma2(acc[i][2], z2, wB.x); fma2(acc[i][3], z2, wB.y);
                }
            }
#pragma unroll
            for (int i = 0; i < 8; i++) {
                float* hp = Hs + (tys * 8 + i) * 260;
                float2 a0 = unpk(acc[i][0]), a1 = unpk(acc[i][1]);
                float2 a2 = unpk(acc[i][2]), a3 = unpk(acc[i][3]);
                *(float4*)(hp + txs * 4) = make_float4(
                    fmaxf(a0.x, 0.f), fmaxf(a0.y, 0.f), fmaxf(a1.x, 0.f), fmaxf(a1.y, 0.f));
                *(float4*)(hp + 128 + txs * 4) = make_float4(
                    fmaxf(a2.x, 0.f), fmaxf(a2.y, 0.f), fmaxf(a3.x, 0.f), fmaxf(a3.y, 0.f));
            }
        }
        __syncthreads();   // z fully consumed -> Zs reusable as P

        // ---- stage 2: Y = H @ W2 + b2, 4-way k-split, serialized reduce ----
        u64 acc[8][4] = {};
        {
            int j0 = q * 64;
#pragma unroll 4
            for (int jj = 0; jj < 64; jj++) {
                int j = j0 + jj;
                ulonglong2 wA = *(const ulonglong2*)(W2s + j * 64 + og * 4);
                ulonglong2 wB = *(const ulonglong2*)(W2s + j * 64 + 32 + og * 4);
#pragma unroll
                for (int i = 0; i < 8; i++) {
                    float h = Hs[(rg + 8 * i) * 260 + j];
                    u64 h2 = pack2(h, h);
                    fma2(acc[i][0], h2, wA.x); fma2(acc[i][1], h2, wA.y);
                    fma2(acc[i][2], h2, wB.x); fma2(acc[i][3], h2, wB.y);
                }
            }
        }
        // serialized partial accumulation into P (= Zs)
        for (int s = 1; s <= 3; s++) {
            if (q == s) {
#pragma unroll
                for (int i = 0; i < 8; i++) {
                    int row = rg + 8 * i;
                    float2 a0 = unpk(acc[i][0]), a1 = unpk(acc[i][1]);
                    float2 a2 = unpk(acc[i][2]), a3 = unpk(acc[i][3]);
                    float4 v0 = make_float4(a0.x, a0.y, a1.x, a1.y);
                    float4 v1 = make_float4(a2.x, a2.y, a3.x, a3.y);
                    float* p0 = Zs + row * 68 + og * 4;
                    float* p1 = Zs + row * 68 + 32 + og * 4;
                    if (s > 1) {
                        float4 e0 = *(float4*)p0, e1 = *(float4*)p1;
                        v0.x += e0.x; v0.y += e0.y; v0.z += e0.z; v0.w += e0.w;
                        v1.x += e1.x; v1.y += e1.y; v1.z += e1.z; v1.w += e1.w;
                    }
                    *(float4*)p0 = v0; *(float4*)p1 = v1;
                }
            }
            __syncthreads();
        }
        if (q == 0) {
            float4 bv0 = *(const float4*)(b2s + og * 4);
            float4 bv1 = *(const float4*)(b2s + 32 + og * 4);
#pragma unroll
            for (int i = 0; i < 8; i++) {
                int row = rg + 8 * i;
                float* p0 = Zs + row * 68 + og * 4;
                float* p1 = Zs + row * 68 + 32 + og * 4;
                float4 e0 = *(float4*)p0, e1 = *(float4*)p1;
                float2 a0 = unpk(acc[i][0]), a1 = unpk(acc[i][1]);
                float2 a2 = unpk(acc[i][2]), a3 = unpk(acc[i][3]);
                e0.x += a0.x + bv0.x; e0.y += a0.y + bv0.y;
                e0.z += a1.x + bv0.z; e0.w += a1.y + bv0.w;
                e1.x += a2.x + bv1.x; e1.y += a2.y + bv1.y;
                e1.z += a3.x + bv1.z; e1.w += a3.y + bv1.w;
                *(float4*)p0 = e0; *(float4*)p1 = e1;
            }
        }
        __syncthreads();

        // ---- LayerNorm + output -------------------------------------------
        if (t < 64) {
            const float* y = Zs + t * 68;
            float s = 0.f, s2 = 0.f;
#pragma unroll 8
            for (int c = 0; c < 64; c++) { float v = y[c]; s += v; s2 += v * v; }
            float mu = s * 0.015625f;
            float var = s2 * 0.015625f - mu * mu;
            mus[t] = mu; rss[t] = rsqrtf(var + 1e-5f);
        }
        __syncthreads();
        {
            int row = t >> 2, cg = (t & 3) * 16;
            float mu = mus[row], rs = rss[row];
            const float* y = Zs + row * 68;
            float* op = out + (r0 + (size_t)row) * 64u;
#pragma unroll
            for (int kk = 0; kk < 4; kk++) {
                int c = cg + kk * 4;
                float4 v = *(const float4*)(y + c);
                float4 o;
                o.x = (v.x - mu) * rs * gs[c + 0] + bs[c + 0];
                o.y = (v.y - mu) * rs * gs[c + 1] + bs[c + 1];
                o.z = (v.z - mu) * rs * gs[c + 2] + bs[c + 2];
                o.w = (v.w - mu) * rs * gs[c + 3] + bs[c + 3];
                *(float4*)(op + c) = o;
            }
        }
        __syncthreads();   // Zs(y) consumed before next group's z load
    }
}

// ----------------------------- launch ---------------------------------------
extern "C" void kernel_launch(void* const* d_in, const int* in_sizes, int n_in,
                              void* d_out, int out_size) {
    (void)in_sizes; (void)n_in; (void)out_size;
    const float* x    = (const float*)d_in[0];
    const float* w1re = (const float*)d_in[1];
    const float* w1im = (const float*)d_in[2];
    const float* w2re = (const float*)d_in[3];
    const float* w2im = (const float*)d_in[4];
    const float* ffw1 = (const float*)d_in[5];
    const float* ffb1 = (const float*)d_in[6];
    const float* ffw2 = (const float*)d_in[7];
    const float* ffb2 = (const float*)d_in[8];
    const float* lng  = (const float*)d_in[9];
    const float* lnb  = (const float*)d_in[10];
    float* out = (float*)d_out;

    cudaFuncSetAttribute(k_fwd, cudaFuncAttributeMaxDynamicSharedMemorySize, 49152);
    cudaFuncSetAttribute(k_mix, cudaFuncAttributeMaxDynamicSharedMemorySize, 66560);
    cudaFuncSetAttribute(k_inv, cudaFuncAttributeMaxDynamicSharedMemorySize, 49664);
    cudaFuncSetAttribute(k_ff,  cudaFuncAttributeMaxDynamicSharedMemorySize, 217344);

    k_basis<<<64, 256>>>();
    k_wt<<<512, 256>>>(w1re, w1im, w2re, w2im);

    // y-path
    k_fwd<<<2048, 256, 49152>>>(x, 0);
    k_mix<<<dim3(64, 32), 256, 66560>>>(0);
    k_inv<<<4096, 256, 49664>>>(0);

    // x-path (accumulates into Z)
    k_fwd<<<2048, 256, 49152>>>(x, 1);
    k_mix<<<dim3(64, 32), 256, 66560>>>(1);
    k_inv<<<4096, 256, 49664>>>(1);

    k_ff<<<2048, 256, 217344>>>(ffw1, ffb1, ffw2, ffb2, lng, lnb, out);
}